// round 16
// baseline (speedup 1.0000x reference)
#include <cuda_runtime.h>
#include <cuda_bf16.h>
#include <stdint.h>
#include <math.h>

#define BB   8
#define NN   4096
#define DD   64
#define KNN  20
#define OO   64

// ---------------- scratch (__device__ globals: allocation-free) ----------------
__device__ float g_sq[BB*NN];
__device__ float g_y [BB*NN*OO];
__device__ float g_z [BB*NN*OO];
__device__ int   g_idx[BB*NN*KNN];
__device__ float g_h [BB*NN*OO];
__device__ float g_psum[128*OO];
__device__ float g_psq [128*OO];
__device__ float g_a [OO];
__device__ float g_bb2[OO];
__device__ float g_dummy;
// bf16x2 split layout, k-major per point, 128 cols: [hi(64) | lo(64)]
// dot3(a,b) = a_hi·b_hi + a_lo·b_hi + a_hi·b_lo  (fragment-reuse bf16x3)
__device__ __nv_bfloat16 g_x[(size_t)BB*NN*128];

__device__ __forceinline__ uint32_t smem_u32(const void* p) {
    uint32_t a;
    asm("{ .reg .u64 t; cvta.to.shared.u64 t, %1; cvt.u32.u64 %0, t; }" : "=r"(a) : "l"(p));
    return a;
}
__device__ __forceinline__ uint32_t pack_bf2(__nv_bfloat16 a, __nv_bfloat16 b) {
    return (uint32_t)__bfloat16_as_ushort(a) | ((uint32_t)__bfloat16_as_ushort(b) << 16);
}
__device__ __forceinline__ void cp16(uint32_t dst, const void* src) {
    asm volatile("cp.async.cg.shared.global [%0], [%1], 16;" :: "r"(dst), "l"(src) : "memory");
}
#define CP_COMMIT() asm volatile("cp.async.commit_group;" ::: "memory")
#define CP_WAIT0()  asm volatile("cp.async.wait_group 0;" ::: "memory")
#define CP_WAIT1()  asm volatile("cp.async.wait_group 1;" ::: "memory")

// ---------------- dummy: steers ncu's skip-5 capture onto knn ------------------
__global__ void dummy_kernel()
{
    if (threadIdx.x > 1000) g_dummy = 1.f;   // never true (32 threads)
}

// ---------------- kernel 1: sumsq, y, z, and [hi|lo] split layout --------------
__global__ __launch_bounds__(128) void prep_kernel(const float* __restrict__ x,
                                                   const float* __restrict__ w)
{
    __shared__ float ws[64*128];
    int tid = threadIdx.x;
    #pragma unroll
    for (int i = 0; i < 64; i++) ws[i*128 + tid] = w[i*128 + tid];
    __syncthreads();

    int b = blockIdx.y;
    int n = blockIdx.x * 128 + tid;
    const float* xb = x + b * (DD*NN);

    float p[DD];
    float sq = 0.f;
    #pragma unroll
    for (int d = 0; d < DD; d++) { p[d] = xb[d*NN + n]; sq = fmaf(p[d], p[d], sq); }
    g_sq[b*NN + n] = sq;

    uint4* pa = (uint4*)(g_x + (size_t)(b*NN + n)*128);
    #pragma unroll
    for (int d = 0; d < DD; d += 8) {
        uint32_t hv[4], lv[4];
        #pragma unroll
        for (int j = 0; j < 4; j++) {
            float v0 = p[d + 2*j], v1 = p[d + 2*j + 1];
            __nv_bfloat16 h0 = __float2bfloat16(v0);
            __nv_bfloat16 h1 = __float2bfloat16(v1);
            __nv_bfloat16 l0 = __float2bfloat16(v0 - __bfloat162float(h0));
            __nv_bfloat16 l1 = __float2bfloat16(v1 - __bfloat162float(h1));
            hv[j] = pack_bf2(h0, h1);
            lv[j] = pack_bf2(l0, l1);
        }
        int c = d >> 3;
        pa[c]     = make_uint4(hv[0], hv[1], hv[2], hv[3]);
        pa[8 + c] = make_uint4(lv[0], lv[1], lv[2], lv[3]);
    }

    float* yp = g_y + (b*NN + n)*OO;
    float* zp = g_z + (b*NN + n)*OO;
    #pragma unroll 2
    for (int o = 0; o < OO; o += 4) {
        float ya[4], za[4];
        #pragma unroll
        for (int j = 0; j < 4; j++) { ya[j] = 0.f; za[j] = 0.f; }
        #pragma unroll
        for (int d = 0; d < DD; d++) {
            float pd = p[d];
            #pragma unroll
            for (int j = 0; j < 4; j++) {
                float w1 = ws[(o+j)*128 + d];
                float w2 = ws[(o+j)*128 + 64 + d];
                ya[j] = fmaf(pd, w1, ya[j]);
                za[j] = fmaf(pd, w2 - w1, za[j]);
            }
        }
        *(float4*)&yp[o] = make_float4(ya[0], ya[1], ya[2], ya[3]);
        *(float4*)&zp[o] = make_float4(za[0], za[1], za[2], za[3]);
    }
}

// ---------------- kernel 2: HMMA Gram + pipelined warp top-20 ------------------
// smem layout: bf16 tiles use 272B row stride (68 words = 4 mod 32: conflict-free
// ldmatrix); sD uses 132-float row stride
#define SM_A   0                 // 128 rows * 272B = 34816
#define SM_B0  34816
#define SM_B1  69632
#define SM_SQ  104448            // float sqs[2][128]
#define SM_D   105472            // float sD[128][132] = 67584
#define SM_TOT 173056

// warp-cooperative scan of one staged tile: warp w sweeps rows w*4..w*4+3,
// float2 per lane (64 cols/ballot); survivors via warp-uniform ballot+shfl.
__device__ __forceinline__ void scan_tile(const float* __restrict__ sD,
                                          int w, int lane, int m0,
                                          float (&lv)[4], int (&li)[4])
{
    const unsigned FULL = 0xFFFFFFFFu;
    #pragma unroll
    for (int ri = 0; ri < 4; ri++) {
        const float* rp = &sD[(w*4 + ri)*132];
        float T = __shfl_sync(FULL, lv[ri], 19);
        #pragma unroll
        for (int s = 0; s < 2; s++) {
            float2 v = *(const float2*)&rp[s*64 + lane*2];
            float cmin = fminf(v.x, v.y);
            unsigned surv = __ballot_sync(FULL, cmin < T);
            while (surv) {
                int src = __ffs((int)surv) - 1; surv &= surv - 1;
                float cv0 = __shfl_sync(FULL, v.x, src);
                float cv1 = __shfl_sync(FULL, v.y, src);
                const int cbase2 = m0 + s*64 + src*2;
                if (cv0 < T) {
                    unsigned gt = __ballot_sync(FULL, lv[ri] > cv0) & 0xFFFFFu;
                    int p = __ffs((int)gt) - 1;
                    float sv = __shfl_up_sync(FULL, lv[ri], 1);
                    int   si = __shfl_up_sync(FULL, li[ri], 1);
                    if (lane > p && lane < 20) { lv[ri] = sv; li[ri] = si; }
                    if (lane == p)             { lv[ri] = cv0; li[ri] = cbase2; }
                    T = __shfl_sync(FULL, lv[ri], 19);
                }
                if (cv1 < T) {
                    unsigned gt = __ballot_sync(FULL, lv[ri] > cv1) & 0xFFFFFu;
                    int p = __ffs((int)gt) - 1;
                    float sv = __shfl_up_sync(FULL, lv[ri], 1);
                    int   si = __shfl_up_sync(FULL, li[ri], 1);
                    if (lane > p && lane < 20) { lv[ri] = sv; li[ri] = si; }
                    if (lane == p)             { lv[ri] = cv1; li[ri] = cbase2 + 1; }
                    T = __shfl_sync(FULL, lv[ri], 19);
                }
            }
        }
    }
}

__global__ __launch_bounds__(1024, 1) void knn_kernel()
{
    extern __shared__ char smem[];
    const uint32_t sb = smem_u32(smem);
    float* sD  = (float*)(smem + SM_D);
    float* sqs = (float*)(smem + SM_SQ);

    const int tid  = threadIdx.x;
    const int lane = tid & 31;
    const int w    = tid >> 5;          // 0..31
    const int b    = blockIdx.y;
    const int r0   = blockIdx.x * 128;

    // prologue: async B0, then A (plain), then async B1
    {
        const char* gb = (const char*)(g_x + (size_t)(b*NN)*128);
        #pragma unroll
        for (int i = tid; i < 128*16; i += 1024) {
            int p = i >> 4, c = i & 15;
            cp16(sb + SM_B0 + (uint32_t)(p*272 + c*16), gb + p*256 + c*16);
        }
        if (tid < 32) cp16(sb + SM_SQ + (uint32_t)(tid*16), (const char*)(g_sq + b*NN + tid*4));
        CP_COMMIT();
    }
    {
        const char* ga = (const char*)(g_x + (size_t)(b*NN + r0)*128);
        #pragma unroll
        for (int i = tid; i < 128*16; i += 1024) {
            int p = i >> 4, c = i & 15;
            *(uint4*)(smem + SM_A + p*272 + c*16) = *(const uint4*)(ga + p*256 + c*16);
        }
    }
    {
        const char* gb = (const char*)(g_x + (size_t)(b*NN + 128)*128);
        #pragma unroll
        for (int i = tid; i < 128*16; i += 1024) {
            int p = i >> 4, c = i & 15;
            cp16(sb + SM_B1 + (uint32_t)(p*272 + c*16), gb + p*256 + c*16);
        }
        if (tid < 32) cp16(sb + SM_SQ + (uint32_t)(512 + tid*16),
                           (const char*)(g_sq + b*NN + 128 + tid*4));
        CP_COMMIT();
    }

    // warp-distributed top-20 lists: lane l holds element l (ascending) of the
    // row's list; warp owns 4 rows (w*4 .. w*4+3)
    float lv[4];
    int   li[4];
    #pragma unroll
    for (int j = 0; j < 4; j++) { lv[j] = 3.4e38f; li[j] = 0; }

    // 8x4 warp tiling for MMA: warp owns rows rg*16..+15, cols cg*32..+31
    const int rg = w >> 2;              // 0..7
    const int cg = w & 3;               // 0..3

    // ldmatrix lane addressing: mm = matrix index (l>>3), rr = l&7
    const int mm = lane >> 3, rr = lane & 7;
    const uint32_t aaddr0 = sb + SM_A
        + (uint32_t)((rg*16 + ((mm & 1) << 3) + rr) * 272)
        + (uint32_t)(((mm & 2) ? 8 : 0) * 2);
    const uint32_t baddr_row = (uint32_t)((cg*32 + ((mm & 2) ? 8 : 0) + rr) * 272)
                             + (uint32_t)(((mm & 1) ? 8 : 0) * 2);

    for (int t = 0; t < 32; t++) {
        const int cur = t & 1;
        const int m0  = t * 128;

        // B(t) resident (leave B(t+1) in flight when it exists)
        if (t < 30) { CP_WAIT1(); } else { CP_WAIT0(); }
        __syncthreads();         // bar1: B(t) visible; stage(t-1) visible

        // ---- MMA(t): 16 rows x 32 cols per warp; fragment-reuse x3 ----
        float acc[4][4];
        #pragma unroll
        for (int i = 0; i < 4; i++)
            #pragma unroll
            for (int j = 0; j < 4; j++) acc[i][j] = 0.f;

        const uint32_t bbase = sb + (cur ? SM_B1 : SM_B0) + baddr_row;
        #pragma unroll
        for (int ks = 0; ks < 4; ks++) {
            uint32_t ah[4], al[4];
            asm volatile("ldmatrix.sync.aligned.m8n8.x4.shared.b16 {%0,%1,%2,%3}, [%4];"
                : "=r"(ah[0]), "=r"(ah[1]), "=r"(ah[2]), "=r"(ah[3])
                : "r"(aaddr0 + (uint32_t)(ks*32)));
            asm volatile("ldmatrix.sync.aligned.m8n8.x4.shared.b16 {%0,%1,%2,%3}, [%4];"
                : "=r"(al[0]), "=r"(al[1]), "=r"(al[2]), "=r"(al[3])
                : "r"(aaddr0 + (uint32_t)(128 + ks*32)));
            #pragma unroll
            for (int bq = 0; bq < 2; bq++) {
                const uint32_t bb = bbase + (uint32_t)(bq*16*272 + ks*32);
                uint32_t bh[4], bl[4];
                asm volatile("ldmatrix.sync.aligned.m8n8.x4.shared.b16 {%0,%1,%2,%3}, [%4];"
                    : "=r"(bh[0]), "=r"(bh[1]), "=r"(bh[2]), "=r"(bh[3])
                    : "r"(bb));
                asm volatile("ldmatrix.sync.aligned.m8n8.x4.shared.b16 {%0,%1,%2,%3}, [%4];"
                    : "=r"(bl[0]), "=r"(bl[1]), "=r"(bl[2]), "=r"(bl[3])
                    : "r"(bb + 128u));
                #pragma unroll
                for (int h = 0; h < 2; h++) {
                    float* A0 = acc[2*bq + h];
                    uint32_t bx = h ? bh[2] : bh[0];
                    uint32_t by = h ? bh[3] : bh[1];
                    uint32_t bu = h ? bl[2] : bl[0];
                    uint32_t bv = h ? bl[3] : bl[1];
                    asm volatile("mma.sync.aligned.m16n8k16.row.col.f32.bf16.bf16.f32 "
                        "{%0,%1,%2,%3},{%4,%5,%6,%7},{%8,%9},{%0,%1,%2,%3};"
                        : "+f"(A0[0]), "+f"(A0[1]), "+f"(A0[2]), "+f"(A0[3])
                        : "r"(ah[0]), "r"(ah[1]), "r"(ah[2]), "r"(ah[3]), "r"(bx), "r"(by));
                    asm volatile("mma.sync.aligned.m16n8k16.row.col.f32.bf16.bf16.f32 "
                        "{%0,%1,%2,%3},{%4,%5,%6,%7},{%8,%9},{%0,%1,%2,%3};"
                        : "+f"(A0[0]), "+f"(A0[1]), "+f"(A0[2]), "+f"(A0[3])
                        : "r"(al[0]), "r"(al[1]), "r"(al[2]), "r"(al[3]), "r"(bx), "r"(by));
                    asm volatile("mma.sync.aligned.m16n8k16.row.col.f32.bf16.bf16.f32 "
                        "{%0,%1,%2,%3},{%4,%5,%6,%7},{%8,%9},{%0,%1,%2,%3};"
                        : "+f"(A0[0]), "+f"(A0[1]), "+f"(A0[2]), "+f"(A0[3])
                        : "r"(ah[0]), "r"(ah[1]), "r"(ah[2]), "r"(ah[3]), "r"(bu), "r"(bv));
                }
            }
        }

        // ---- scan(t-1): overlaps the HMMA chain above (independent regs) ----
        if (t > 0) scan_tile(sD, w, lane, m0 - 128, lv, li);

        __syncthreads();         // bar2: sD(t-1) reads done; B(t-1) buffer free

        // ---- stage(t): criterion = sq[m] - 2*dot  (row stride 132 floats) ----
        {
            const int rw = rg*16 + (lane >> 2);
            const int cb = (lane & 3) * 2;
            const float* sqc = sqs + cur*128;
            #pragma unroll
            for (int ct = 0; ct < 4; ct++) {
                int col = cg*32 + ct*8 + cb;
                float s0 = sqc[col], s1 = sqc[col+1];
                *(float2*)&sD[rw*132 + col] =
                    make_float2(fmaf(-2.f, acc[ct][0], s0), fmaf(-2.f, acc[ct][1], s1));
                *(float2*)&sD[(rw+8)*132 + col] =
                    make_float2(fmaf(-2.f, acc[ct][2], s0), fmaf(-2.f, acc[ct][3], s1));
            }
        }

        // ---- prefetch B(t+2) into the buffer MMA(t) just released ----
        if (t + 2 < 32) {
            const int mn = (t + 2) * 128;
            const char* gb = (const char*)(g_x + (size_t)(b*NN + mn)*128);
            const uint32_t bdst = sb + (cur ? SM_B1 : SM_B0);
            #pragma unroll
            for (int i = tid; i < 128*16; i += 1024) {
                int p = i >> 4, c = i & 15;
                cp16(bdst + (uint32_t)(p*272 + c*16), gb + p*256 + c*16);
            }
            if (tid < 32) cp16(sb + SM_SQ + (uint32_t)(cur*512 + tid*16),
                               (const char*)(g_sq + b*NN + mn + tid*4));
            CP_COMMIT();
        }
    }

    __syncthreads();             // stage(31) visible
    scan_tile(sD, w, lane, 31*128, lv, li);

    // write out: lanes 0..19 hold the row's top-20 (ascending)
    #pragma unroll
    for (int ri = 0; ri < 4; ri++) {
        if (lane < KNN)
            g_idx[(b*NN + r0 + w*4 + ri)*KNN + lane] = li[ri];
    }
}

// ---------------- kernel 3: gather-max + h + BN partial sums -------------------
__global__ __launch_bounds__(256) void hmax_kernel()
{
    int tid = threadIdx.x;
    int warp = tid >> 5, lane = tid & 31;
    int b = blockIdx.y;
    int nbase = blockIdx.x * 256 + warp * 32;
    const float* yb = g_y + b*NN*OO;

    float s0 = 0.f, s1 = 0.f, q0 = 0.f, q1 = 0.f;
    for (int i = 0; i < 32; i++) {
        int n = nbase + i;
        const int* ip = g_idx + (b*NN + n)*KNN;
        float m0v = -3.4e38f, m1v = -3.4e38f;
        #pragma unroll
        for (int k = 0; k < KNN; k++) {
            int m = ip[k];
            const float* yr = yb + m*OO;
            m0v = fmaxf(m0v, yr[lane]);
            m1v = fmaxf(m1v, yr[lane + 32]);
        }
        const float* zr = g_z + (b*NN + n)*OO;
        float h0 = zr[lane]      + m0v;
        float h1 = zr[lane + 32] + m1v;
        g_h[(b*NN + n)*OO + lane]      = h0;
        g_h[(b*NN + n)*OO + lane + 32] = h1;
        s0 += h0; s1 += h1;
        q0 = fmaf(h0, h0, q0); q1 = fmaf(h1, h1, q1);
    }

    __shared__ float ps[8][64], pq[8][64];
    ps[warp][lane]      = s0; ps[warp][lane + 32] = s1;
    pq[warp][lane]      = q0; pq[warp][lane + 32] = q1;
    __syncthreads();
    if (tid < 64) {
        float S = 0.f, Q = 0.f;
        #pragma unroll
        for (int wr = 0; wr < 8; wr++) { S += ps[wr][tid]; Q += pq[wr][tid]; }
        int blk = b*16 + blockIdx.x;
        g_psum[blk*64 + tid] = S;
        g_psq [blk*64 + tid] = Q;
    }
}

// ---------------- kernel 4: deterministic fp64 stats reduce (64 blocks) --------
__global__ __launch_bounds__(128) void stats_kernel(const float* __restrict__ gamma,
                                                    const float* __restrict__ beta)
{
    __shared__ double sS[128], sQ[128];
    const int ch = blockIdx.x;          // 0..63
    const int t  = threadIdx.x;         // 0..127
    sS[t] = (double)g_psum[t*64 + ch];
    sQ[t] = (double)g_psq [t*64 + ch];
    __syncthreads();
    #pragma unroll
    for (int s = 64; s > 0; s >>= 1) {
        if (t < s) { sS[t] += sS[t + s]; sQ[t] += sQ[t + s]; }
        __syncthreads();
    }
    if (t == 0) {
        double cnt  = (double)(BB * NN);
        double mean = sS[0] / cnt;
        double var  = sQ[0] / cnt - mean * mean;
        float inv = (float)(1.0 / sqrt(var + 1e-5));
        float a = gamma[ch] * inv;
        g_a  [ch] = a;
        g_bb2[ch] = beta[ch] - (float)mean * a;
    }
}

// ---------------- kernel 5: BN affine + exact GELU + transpose -----------------
__global__ __launch_bounds__(256) void final_kernel(float* __restrict__ out)
{
    __shared__ float t[64][65];
    int tid = threadIdx.x;
    int b = blockIdx.y;
    int n0 = blockIdx.x * 64;
    const float* hb = g_h + b*NN*OO;

    #pragma unroll
    for (int it = 0; it < 16; it++) {
        int idx = it*256 + tid;
        int nl = idx >> 6, o = idx & 63;
        t[nl][o] = hb[(n0 + nl)*OO + o];
    }
    __syncthreads();

    float* ob = out + b*OO*NN;
    #pragma unroll
    for (int it = 0; it < 16; it++) {
        int idx = it*256 + tid;
        int o = idx >> 6, nl = idx & 63;
        float v = t[nl][o] * g_a[o] + g_bb2[o];
        ob[o*NN + n0 + nl] = 0.5f * v * (1.f + erff(v * 0.70710678118654752f));
    }
}

// ---------------- launch --------------------------------------------------------
extern "C" void kernel_launch(void* const* d_in, const int* in_sizes, int n_in,
                              void* d_out, int out_size)
{
    const float* x     = (const float*)d_in[0];
    const float* w     = (const float*)d_in[1];
    const float* gamma = (const float*)d_in[2];
    const float* beta  = (const float*)d_in[3];
    float* out = (float*)d_out;

    cudaFuncSetAttribute(knn_kernel, cudaFuncAttributeMaxDynamicSharedMemorySize, SM_TOT);

    prep_kernel <<<dim3(NN/128, BB), 128>>>(x, w);
    dummy_kernel<<<1, 32>>>();
    dummy_kernel<<<1, 32>>>();
    knn_kernel  <<<dim3(NN/128, BB), 1024, SM_TOT>>>();
    hmax_kernel <<<dim3(NN/256, BB), 256>>>();
    stats_kernel<<<64, 128>>>(gamma, beta);
    final_kernel<<<dim3(NN/64, BB), 256>>>(out);
}

// round 17
// speedup vs baseline: 1.0896x; 1.0896x over previous
#include <cuda_runtime.h>
#include <cuda_bf16.h>
#include <stdint.h>
#include <math.h>

#define BB   8
#define NN   4096
#define DD   64
#define KNN  20
#define OO   64

// ---------------- scratch (__device__ globals: allocation-free) ----------------
__device__ float g_sq[BB*NN];
__device__ float g_y [BB*NN*OO];
__device__ float g_z [BB*NN*OO];
__device__ int   g_idx[BB*NN*KNN];
__device__ float g_h [BB*NN*OO];
__device__ float g_psum[256*OO];
__device__ float g_psq [256*OO];
__device__ float g_a [OO];
__device__ float g_bb2[OO];
__device__ float g_dummy;
// bf16x2 split layout, k-major per point, 128 cols: [hi(64) | lo(64)]
// dot3(a,b) = a_hi·b_hi + a_lo·b_hi + a_hi·b_lo  (fragment-reuse bf16x3)
__device__ __nv_bfloat16 g_x[(size_t)BB*NN*128];

__device__ __forceinline__ uint32_t smem_u32(const void* p) {
    uint32_t a;
    asm("{ .reg .u64 t; cvta.to.shared.u64 t, %1; cvt.u32.u64 %0, t; }" : "=r"(a) : "l"(p));
    return a;
}
__device__ __forceinline__ uint32_t pack_bf2(__nv_bfloat16 a, __nv_bfloat16 b) {
    return (uint32_t)__bfloat16_as_ushort(a) | ((uint32_t)__bfloat16_as_ushort(b) << 16);
}
__device__ __forceinline__ void cp16(uint32_t dst, const void* src) {
    asm volatile("cp.async.cg.shared.global [%0], [%1], 16;" :: "r"(dst), "l"(src) : "memory");
}
#define CP_COMMIT() asm volatile("cp.async.commit_group;" ::: "memory")
#define CP_WAIT0()  asm volatile("cp.async.wait_group 0;" ::: "memory")
#define CP_WAIT1()  asm volatile("cp.async.wait_group 1;" ::: "memory")

// ---------------- dummy: steers ncu's skip-5 capture onto knn ------------------
__global__ void dummy_kernel()
{
    if (threadIdx.x > 1000) g_dummy = 1.f;   // never true (32 threads)
}

// ---------------- kernel 1: sumsq, y, z, and [hi|lo] split layout --------------
__global__ __launch_bounds__(128) void prep_kernel(const float* __restrict__ x,
                                                   const float* __restrict__ w)
{
    __shared__ float ws[64*128];
    int tid = threadIdx.x;
    #pragma unroll
    for (int i = 0; i < 64; i++) ws[i*128 + tid] = w[i*128 + tid];
    __syncthreads();

    int b = blockIdx.y;
    int n = blockIdx.x * 128 + tid;
    const float* xb = x + b * (DD*NN);

    float p[DD];
    float sq = 0.f;
    #pragma unroll
    for (int d = 0; d < DD; d++) { p[d] = xb[d*NN + n]; sq = fmaf(p[d], p[d], sq); }
    g_sq[b*NN + n] = sq;

    uint4* pa = (uint4*)(g_x + (size_t)(b*NN + n)*128);
    #pragma unroll
    for (int d = 0; d < DD; d += 8) {
        uint32_t hv[4], lv[4];
        #pragma unroll
        for (int j = 0; j < 4; j++) {
            float v0 = p[d + 2*j], v1 = p[d + 2*j + 1];
            __nv_bfloat16 h0 = __float2bfloat16(v0);
            __nv_bfloat16 h1 = __float2bfloat16(v1);
            __nv_bfloat16 l0 = __float2bfloat16(v0 - __bfloat162float(h0));
            __nv_bfloat16 l1 = __float2bfloat16(v1 - __bfloat162float(h1));
            hv[j] = pack_bf2(h0, h1);
            lv[j] = pack_bf2(l0, l1);
        }
        int c = d >> 3;
        pa[c]     = make_uint4(hv[0], hv[1], hv[2], hv[3]);
        pa[8 + c] = make_uint4(lv[0], lv[1], lv[2], lv[3]);
    }

    float* yp = g_y + (b*NN + n)*OO;
    float* zp = g_z + (b*NN + n)*OO;
    #pragma unroll 2
    for (int o = 0; o < OO; o += 4) {
        float ya[4], za[4];
        #pragma unroll
        for (int j = 0; j < 4; j++) { ya[j] = 0.f; za[j] = 0.f; }
        #pragma unroll
        for (int d = 0; d < DD; d++) {
            float pd = p[d];
            #pragma unroll
            for (int j = 0; j < 4; j++) {
                float w1 = ws[(o+j)*128 + d];
                float w2 = ws[(o+j)*128 + 64 + d];
                ya[j] = fmaf(pd, w1, ya[j]);
                za[j] = fmaf(pd, w2 - w1, za[j]);
            }
        }
        *(float4*)&yp[o] = make_float4(ya[0], ya[1], ya[2], ya[3]);
        *(float4*)&zp[o] = make_float4(za[0], za[1], za[2], za[3]);
    }
}

// ---------------- kernel 2: HMMA Gram (fragment-reuse x3) + warp top-20 --------
// (R15-proven structure: MMA -> stage -> scan, 2 barriers/tile)
#define SM_A   0                 // 128 rows * 272B = 34816
#define SM_B0  34816
#define SM_B1  69632
#define SM_SQ  104448            // float sqs[2][128]
#define SM_D   105472            // float sD[128][132] = 67584
#define SM_TOT 173056

__global__ __launch_bounds__(1024, 1) void knn_kernel()
{
    extern __shared__ char smem[];
    const uint32_t sb = smem_u32(smem);
    float* sD  = (float*)(smem + SM_D);
    float* sqs = (float*)(smem + SM_SQ);

    const int tid  = threadIdx.x;
    const int lane = tid & 31;
    const int w    = tid >> 5;          // 0..31
    const int b    = blockIdx.y;
    const int r0   = blockIdx.x * 128;
    const unsigned FULL = 0xFFFFFFFFu;

    // async copy of B tile 0 + sq 0 first (deepest prefetch)
    {
        const char* gb = (const char*)(g_x + (size_t)(b*NN)*128);
        #pragma unroll
        for (int i = tid; i < 128*16; i += 1024) {
            int p = i >> 4, c = i & 15;
            cp16(sb + SM_B0 + (uint32_t)(p*272 + c*16), gb + p*256 + c*16);
        }
        if (tid < 32) cp16(sb + SM_SQ + (uint32_t)(tid*16), (const char*)(g_sq + b*NN + tid*4));
        CP_COMMIT();
    }
    // A rows r0..r0+127 -> smem (plain copy, overlaps cp.async)
    {
        const char* ga = (const char*)(g_x + (size_t)(b*NN + r0)*128);
        #pragma unroll
        for (int i = tid; i < 128*16; i += 1024) {
            int p = i >> 4, c = i & 15;
            *(uint4*)(smem + SM_A + p*272 + c*16) = *(const uint4*)(ga + p*256 + c*16);
        }
    }

    // warp-distributed top-20 lists: lane l holds element l (ascending) of the
    // row's list; warp owns 4 rows (w*4 .. w*4+3)
    float lv[4];
    int   li[4];
    #pragma unroll
    for (int j = 0; j < 4; j++) { lv[j] = 3.4e38f; li[j] = 0; }

    // 8x4 warp tiling for MMA: warp owns rows rg*16..+15, cols cg*32..+31
    const int rg = w >> 2;              // 0..7
    const int cg = w & 3;               // 0..3

    // ldmatrix lane addressing: mm = matrix index (l>>3), rr = l&7
    const int mm = lane >> 3, rr = lane & 7;
    const uint32_t aaddr0 = sb + SM_A
        + (uint32_t)((rg*16 + ((mm & 1) << 3) + rr) * 272)
        + (uint32_t)(((mm & 2) ? 8 : 0) * 2);
    const uint32_t baddr_row = (uint32_t)((cg*32 + ((mm & 2) ? 8 : 0) + rr) * 272)
                             + (uint32_t)(((mm & 1) ? 8 : 0) * 2);

    for (int t = 0; t < 32; t++) {
        const int cur = t & 1;
        const int nxt = cur ^ 1;
        const int m0  = t * 128;

        // prefetch B tile t+1 + sq into the other buffer (async, overlapped
        // with the previous tile's scan — no barrier between them)
        if (t + 1 < 32) {
            const int mn = m0 + 128;
            const char* gb = (const char*)(g_x + (size_t)(b*NN + mn)*128);
            const uint32_t bdst = sb + (nxt ? SM_B1 : SM_B0);
            #pragma unroll
            for (int i = tid; i < 128*16; i += 1024) {
                int p = i >> 4, c = i & 15;
                cp16(bdst + (uint32_t)(p*272 + c*16), gb + p*256 + c*16);
            }
            if (tid < 32) cp16(sb + SM_SQ + (uint32_t)(nxt*512 + tid*16),
                               (const char*)(g_sq + b*NN + mn + tid*4));
            CP_COMMIT();
            CP_WAIT1();          // tile t resident; t+1 still in flight
        } else {
            CP_WAIT0();
        }
        __syncthreads();         // B-tile t visible to all; sD(t-1) reads done

        // MMA: 16 rows x 32 cols per warp; 3-term split via fragment reuse:
        //   acc += A_hi B_hi + A_lo B_hi + A_hi B_lo   (4 k-chunks of 16)
        float acc[4][4];
        #pragma unroll
        for (int i = 0; i < 4; i++)
            #pragma unroll
            for (int j = 0; j < 4; j++) acc[i][j] = 0.f;

        const uint32_t bbase = sb + (cur ? SM_B1 : SM_B0) + baddr_row;
        #pragma unroll
        for (int ks = 0; ks < 4; ks++) {
            uint32_t ah[4], al[4];
            asm volatile("ldmatrix.sync.aligned.m8n8.x4.shared.b16 {%0,%1,%2,%3}, [%4];"
                : "=r"(ah[0]), "=r"(ah[1]), "=r"(ah[2]), "=r"(ah[3])
                : "r"(aaddr0 + (uint32_t)(ks*32)));
            asm volatile("ldmatrix.sync.aligned.m8n8.x4.shared.b16 {%0,%1,%2,%3}, [%4];"
                : "=r"(al[0]), "=r"(al[1]), "=r"(al[2]), "=r"(al[3])
                : "r"(aaddr0 + (uint32_t)(128 + ks*32)));
            #pragma unroll
            for (int bq = 0; bq < 2; bq++) {
                const uint32_t bb = bbase + (uint32_t)(bq*16*272 + ks*32);
                uint32_t bh[4], bl[4];
                asm volatile("ldmatrix.sync.aligned.m8n8.x4.shared.b16 {%0,%1,%2,%3}, [%4];"
                    : "=r"(bh[0]), "=r"(bh[1]), "=r"(bh[2]), "=r"(bh[3])
                    : "r"(bb));
                asm volatile("ldmatrix.sync.aligned.m8n8.x4.shared.b16 {%0,%1,%2,%3}, [%4];"
                    : "=r"(bl[0]), "=r"(bl[1]), "=r"(bl[2]), "=r"(bl[3])
                    : "r"(bb + 128u));
                #pragma unroll
                for (int h = 0; h < 2; h++) {
                    float* A0 = acc[2*bq + h];
                    uint32_t bx = h ? bh[2] : bh[0];
                    uint32_t by = h ? bh[3] : bh[1];
                    uint32_t bu = h ? bl[2] : bl[0];
                    uint32_t bv = h ? bl[3] : bl[1];
                    asm volatile("mma.sync.aligned.m16n8k16.row.col.f32.bf16.bf16.f32 "
                        "{%0,%1,%2,%3},{%4,%5,%6,%7},{%8,%9},{%0,%1,%2,%3};"
                        : "+f"(A0[0]), "+f"(A0[1]), "+f"(A0[2]), "+f"(A0[3])
                        : "r"(ah[0]), "r"(ah[1]), "r"(ah[2]), "r"(ah[3]), "r"(bx), "r"(by));
                    asm volatile("mma.sync.aligned.m16n8k16.row.col.f32.bf16.bf16.f32 "
                        "{%0,%1,%2,%3},{%4,%5,%6,%7},{%8,%9},{%0,%1,%2,%3};"
                        : "+f"(A0[0]), "+f"(A0[1]), "+f"(A0[2]), "+f"(A0[3])
                        : "r"(al[0]), "r"(al[1]), "r"(al[2]), "r"(al[3]), "r"(bx), "r"(by));
                    asm volatile("mma.sync.aligned.m16n8k16.row.col.f32.bf16.bf16.f32 "
                        "{%0,%1,%2,%3},{%4,%5,%6,%7},{%8,%9},{%0,%1,%2,%3};"
                        : "+f"(A0[0]), "+f"(A0[1]), "+f"(A0[2]), "+f"(A0[3])
                        : "r"(ah[0]), "r"(ah[1]), "r"(ah[2]), "r"(ah[3]), "r"(bu), "r"(bv));
                }
            }
        }

        // stage criterion = sq[m] - 2*dot  (row stride 132 floats)
        {
            const int rw = rg*16 + (lane >> 2);
            const int cb = (lane & 3) * 2;
            const float* sqc = sqs + cur*128;
            #pragma unroll
            for (int ct = 0; ct < 4; ct++) {
                int col = cg*32 + ct*8 + cb;
                float s0 = sqc[col], s1 = sqc[col+1];
                *(float2*)&sD[rw*132 + col] =
                    make_float2(fmaf(-2.f, acc[ct][0], s0), fmaf(-2.f, acc[ct][1], s1));
                *(float2*)&sD[(rw+8)*132 + col] =
                    make_float2(fmaf(-2.f, acc[ct][2], s0), fmaf(-2.f, acc[ct][3], s1));
            }
        }
        __syncthreads();         // sD(t) complete before scan

        // scan: warp-cooperative, float2 per lane (64 cols per ballot).
        // Survivors inserted via warp-uniform ballot+shfl (no divergent bubble).
        #pragma unroll
        for (int ri = 0; ri < 4; ri++) {
            const float* rp = &sD[(w*4 + ri)*132];
            float T = __shfl_sync(FULL, lv[ri], 19);
            #pragma unroll
            for (int s = 0; s < 2; s++) {
                float2 v = *(const float2*)&rp[s*64 + lane*2];
                float cmin = fminf(v.x, v.y);
                unsigned surv = __ballot_sync(FULL, cmin < T);
                while (surv) {
                    int src = __ffs((int)surv) - 1; surv &= surv - 1;
                    float cv0 = __shfl_sync(FULL, v.x, src);
                    float cv1 = __shfl_sync(FULL, v.y, src);
                    const int cbase2 = m0 + s*64 + src*2;
                    if (cv0 < T) {
                        unsigned gt = __ballot_sync(FULL, lv[ri] > cv0) & 0xFFFFFu;
                        int p = __ffs((int)gt) - 1;
                        float sv = __shfl_up_sync(FULL, lv[ri], 1);
                        int   si = __shfl_up_sync(FULL, li[ri], 1);
                        if (lane > p && lane < 20) { lv[ri] = sv; li[ri] = si; }
                        if (lane == p)             { lv[ri] = cv0; li[ri] = cbase2; }
                        T = __shfl_sync(FULL, lv[ri], 19);
                    }
                    if (cv1 < T) {
                        unsigned gt = __ballot_sync(FULL, lv[ri] > cv1) & 0xFFFFFu;
                        int p = __ffs((int)gt) - 1;
                        float sv = __shfl_up_sync(FULL, lv[ri], 1);
                        int   si = __shfl_up_sync(FULL, li[ri], 1);
                        if (lane > p && lane < 20) { lv[ri] = sv; li[ri] = si; }
                        if (lane == p)             { lv[ri] = cv1; li[ri] = cbase2 + 1; }
                        T = __shfl_sync(FULL, lv[ri], 19);
                    }
                }
            }
        }
        // NOTE: no barrier here — scan(t) vs stage(t+1) is ordered by the
        // __syncthreads after CP_WAIT at the top of iteration t+1.
    }

    // write out: lanes 0..19 hold the row's top-20 (ascending)
    #pragma unroll
    for (int ri = 0; ri < 4; ri++) {
        if (lane < KNN)
            g_idx[(b*NN + r0 + w*4 + ri)*KNN + lane] = li[ri];
    }
}

// ---------------- kernel 3: gather-max (float2) + h + BN partial sums ----------
__global__ __launch_bounds__(256) void hmax_kernel()
{
    int tid = threadIdx.x;
    int warp = tid >> 5, lane = tid & 31;
    int b = blockIdx.y;
    int nbase = blockIdx.x * 128 + warp * 16;
    const float2* yb2 = (const float2*)(g_y + (size_t)b*NN*OO);

    float2 s = make_float2(0.f, 0.f), q = make_float2(0.f, 0.f);
    for (int i = 0; i < 16; i++) {
        int n = nbase + i;
        const int* ip = g_idx + (b*NN + n)*KNN;
        float2 mv = make_float2(-3.4e38f, -3.4e38f);
        #pragma unroll
        for (int k = 0; k < KNN; k++) {
            int m = ip[k];
            float2 yv = yb2[m*32 + lane];
            mv.x = fmaxf(mv.x, yv.x);
            mv.y = fmaxf(mv.y, yv.y);
        }
        float2 zv = ((const float2*)(g_z + (size_t)(b*NN + n)*OO))[lane];
        float2 h = make_float2(zv.x + mv.x, zv.y + mv.y);
        ((float2*)(g_h + (size_t)(b*NN + n)*OO))[lane] = h;
        s.x += h.x; s.y += h.y;
        q.x = fmaf(h.x, h.x, q.x); q.y = fmaf(h.y, h.y, q.y);
    }

    __shared__ float ps[8][64], pq[8][64];
    ps[warp][2*lane] = s.x; ps[warp][2*lane+1] = s.y;
    pq[warp][2*lane] = q.x; pq[warp][2*lane+1] = q.y;
    __syncthreads();
    if (tid < 64) {
        float S = 0.f, Q = 0.f;
        #pragma unroll
        for (int wr = 0; wr < 8; wr++) { S += ps[wr][tid]; Q += pq[wr][tid]; }
        int blk = b*32 + blockIdx.x;
        g_psum[blk*64 + tid] = S;
        g_psq [blk*64 + tid] = Q;
    }
}

// ---------------- kernel 4: deterministic fp64 stats reduce (64 blocks) --------
__global__ __launch_bounds__(256) void stats_kernel(const float* __restrict__ gamma,
                                                    const float* __restrict__ beta)
{
    __shared__ double sS[256], sQ[256];
    const int ch = blockIdx.x;          // 0..63
    const int t  = threadIdx.x;         // 0..255
    sS[t] = (double)g_psum[t*64 + ch];
    sQ[t] = (double)g_psq [t*64 + ch];
    __syncthreads();
    #pragma unroll
    for (int s = 128; s > 0; s >>= 1) {
        if (t < s) { sS[t] += sS[t + s]; sQ[t] += sQ[t + s]; }
        __syncthreads();
    }
    if (t == 0) {
        double cnt  = (double)(BB * NN);
        double mean = sS[0] / cnt;
        double var  = sQ[0] / cnt - mean * mean;
        float inv = (float)(1.0 / sqrt(var + 1e-5));
        float a = gamma[ch] * inv;
        g_a  [ch] = a;
        g_bb2[ch] = beta[ch] - (float)mean * a;
    }
}

// ---------------- kernel 5: BN affine + exact GELU + transpose -----------------
__global__ __launch_bounds__(256) void final_kernel(float* __restrict__ out)
{
    __shared__ float t[64][65];
    int tid = threadIdx.x;
    int b = blockIdx.y;
    int n0 = blockIdx.x * 64;
    const float* hb = g_h + (size_t)b*NN*OO;

    #pragma unroll
    for (int it = 0; it < 16; it++) {
        int idx = it*256 + tid;
        int nl = idx >> 6, o = idx & 63;
        t[nl][o] = hb[(n0 + nl)*OO + o];
    }
    __syncthreads();

    float* ob = out + (size_t)b*OO*NN;
    #pragma unroll
    for (int it = 0; it < 16; it++) {
        int idx = it*256 + tid;
        int o = idx >> 6, nl = idx & 63;
        float v = t[nl][o] * g_a[o] + g_bb2[o];
        ob[o*NN + n0 + nl] = 0.5f * v * (1.f + erff(v * 0.70710678118654752f));
    }
}

// ---------------- launch --------------------------------------------------------
extern "C" void kernel_launch(void* const* d_in, const int* in_sizes, int n_in,
                              void* d_out, int out_size)
{
    const float* x     = (const float*)d_in[0];
    const float* w     = (const float*)d_in[1];
    const float* gamma = (const float*)d_in[2];
    const float* beta  = (const float*)d_in[3];
    float* out = (float*)d_out;

    cudaFuncSetAttribute(knn_kernel, cudaFuncAttributeMaxDynamicSharedMemorySize, SM_TOT);

    prep_kernel <<<dim3(NN/128, BB), 128>>>(x, w);
    dummy_kernel<<<1, 32>>>();
    dummy_kernel<<<1, 32>>>();
    knn_kernel  <<<dim3(NN/128, BB), 1024, SM_TOT>>>();
    hmax_kernel <<<dim3(NN/128, BB), 256>>>();
    stats_kernel<<<64, 256>>>(gamma, beta);
    final_kernel<<<dim3(NN/64, BB), 256>>>(out);
}